// round 8
// baseline (speedup 1.0000x reference)
#include <cuda_runtime.h>
#include <cuda_bf16.h>
#include <cstdint>

#define XN 32
#define CIN 256
#define HIN 56
#define WIN 56
#define S_IN 3136
#define COUT 256
#define HOUT 28
#define WOUT 28
#define S_OUT 784
#define M_TOTAL 25088
#define X_ELEMS (XN * CIN * S_IN)

// M-tile split: tiles [0, NBF) -> bf16 tensor path, [NBF, 196) -> s8 ALU path
#define NTILES 196
#define NBF    125

// Device scratch (no cudaMalloc allowed)
__device__ __align__(16) __nv_bfloat16 g_xq[(size_t)XN * S_IN * CIN];   // 51.4 MB NHWC bf16
__device__ __align__(16) signed char  g_xq8[(size_t)XN * S_IN * CIN];   // 25.7 MB NHWC s8
__device__ __align__(16) __nv_bfloat16 g_wq[(size_t)COUT * 9 * CIN];    // [co][tap][ci] bf16
__device__ __align__(16) signed char  g_wq8[(size_t)COUT * 9 * CIN];    // [co][tap][ci] s8

// ---------------------------------------------------------------------------
// Kernel 1: quantize x (round-half-even, clamp) -> bf16 NHWC + s8 NHWC,
// NCHW -> N(S)C transpose via smem tiles (128 ch x 32 spatial).
// ---------------------------------------------------------------------------
__global__ void quant_x_kernel(const float* __restrict__ x) {
    __shared__ __align__(16) __nv_bfloat16 tile[32 * 130];   // proven conflict-free
    __shared__ __align__(16) signed char  tile8[32 * 132];   // proven conflict-free
    const int n  = blockIdx.z;
    const int c0 = blockIdx.y * 128;
    const int s0 = blockIdx.x * 32;
    const int t  = threadIdx.x;

    const float* xb = x + (size_t)n * CIN * S_IN;
#pragma unroll
    for (int it = 0; it < 16; ++it) {
        int i  = it * 256 + t;
        int cl = i >> 5;   // 0..127
        int sl = i & 31;   // 0..31
        float v = xb[(size_t)(c0 + cl) * S_IN + (s0 + sl)];
        int q = __float2int_rn(v * 20.0f);   // round-half-even == jnp.round
        q = max(-128, min(127, q));
        tile[sl * 130 + cl]  = __float2bfloat16((float)q);  // exact (|q|<=128)
        tile8[sl * 132 + cl] = (signed char)q;
    }
    __syncthreads();

    __nv_bfloat16* ob = g_xq + ((size_t)n * S_IN + s0) * CIN + c0;
#pragma unroll
    for (int it = 0; it < 8; ++it) {
        int u  = it * 256 + t;
        int sl = u >> 6;
        int cu = u & 63;
        uint32_t val = *(const uint32_t*)&tile[sl * 130 + cu * 2];
        *(uint32_t*)&ob[(size_t)sl * CIN + cu * 2] = val;
    }
    signed char* ob8 = g_xq8 + ((size_t)n * S_IN + s0) * CIN + c0;
#pragma unroll
    for (int it = 0; it < 4; ++it) {
        int j  = it * 256 + t;
        int sl = j >> 5;
        int c4 = j & 31;
        uint32_t val = *(const uint32_t*)&tile8[sl * 132 + c4 * 4];
        *(uint32_t*)&ob8[(size_t)sl * CIN + c4 * 4] = val;
    }
}

// ---------------------------------------------------------------------------
// Kernel 2: weights OIHW fp32 (int-valued) -> [co][tap][ci] bf16 + s8
// ---------------------------------------------------------------------------
__global__ void quant_w_kernel(const float* __restrict__ w) {
    int idx = blockIdx.x * blockDim.x + threadIdx.x;
    if (idx >= COUT * 9 * CIN) return;
    int co  = idx / (9 * CIN);
    int r   = idx - co * 9 * CIN;
    int tap = r >> 8;
    int ci  = r & 255;
    int q = __float2int_rn(w[(size_t)co * CIN * 9 + (size_t)ci * 9 + tap]);
    g_wq[idx]  = __float2bfloat16((float)q);
    g_wq8[idx] = (signed char)q;
}

// ---------------------------------------------------------------------------
// Kernel 3: hybrid conv. bf16 HMMA path (tensor pipe) on m-tiles [0,NBF),
// s8 emulated-IMMA path (fma/alu pipes) on m-tiles [NBF,196). One launch so
// both block types co-reside per SM and the two pipes fill concurrently.
// ---------------------------------------------------------------------------
// bf16 path constants (R6, proven)
#define PITCH 144
#define TILEB (128 * PITCH)
#define STGB  (2 * TILEB)
#define SMEMT (2 * STGB)     // 73728 dynamic smem (covers s8 path's 40960)
// s8 path constants (R4, proven)
#define PITCH8 80
#define STG8  (128 * PITCH8) // 10240

__device__ __forceinline__ void cp16(uint32_t dst, const void* src, int sz) {
    asm volatile("cp.async.ca.shared.global [%0], [%1], 16, %2;\n"
                 :: "r"(dst), "l"(src), "r"(sz));
}
#define LDSM4(r0, r1, r2, r3, addr)                                          \
    asm volatile("ldmatrix.sync.aligned.m8n8.x4.shared.b16 {%0,%1,%2,%3}, [%4];" \
                 : "=r"(r0), "=r"(r1), "=r"(r2), "=r"(r3) : "r"(addr))
#define MMABF16(d, a, b0_, b1_)                                               \
    asm volatile(                                                             \
        "mma.sync.aligned.m16n8k16.row.col.f32.bf16.bf16.f32 "               \
        "{%0,%1,%2,%3}, {%4,%5,%6,%7}, {%8,%9}, {%0,%1,%2,%3};\n"            \
        : "+f"(d[0]), "+f"(d[1]), "+f"(d[2]), "+f"(d[3])                     \
        : "r"(a[0]), "r"(a[1]), "r"(a[2]), "r"(a[3]), "r"(b0_), "r"(b1_))
#define MMAS8(d, a, b0_, b1_)                                                 \
    asm volatile(                                                             \
        "mma.sync.aligned.m16n8k32.row.col.s32.s8.s8.s32 "                   \
        "{%0,%1,%2,%3}, {%4,%5,%6,%7}, {%8,%9}, {%0,%1,%2,%3};\n"            \
        : "+r"(d[0]), "+r"(d[1]), "+r"(d[2]), "+r"(d[3])                     \
        : "r"(a[0]), "r"(a[1]), "r"(a[2]), "r"(a[3]), "r"(b0_), "r"(b1_))

// ---- bf16 tensor-path body (verbatim R6) ----
__device__ __forceinline__ void conv_bf16_body(char* dsm, float* __restrict__ out) {
    const uint32_t sbase = (uint32_t)__cvta_generic_to_shared(dsm);
    const int t      = threadIdx.x;
    const int lane   = t & 31;
    const int warp_m = (t >> 5) & 3;
    const int warp_n = t >> 7;
    const int m0     = blockIdx.x * 128;
    const int co0    = blockIdx.y * 128;

    const int lrow  = t >> 1;
    const int lhalf = t & 1;

    int m   = m0 + lrow;
    int n   = m / S_OUT;
    int rem = m - n * S_OUT;
    int ho  = rem / WOUT;
    int wo  = rem - ho * WOUT;
    const int hb = 2 * ho - 1;
    const int wb = 2 * wo - 1;
    const __nv_bfloat16* an = g_xq + (size_t)n * S_IN * CIN + lhalf * 32;
    const __nv_bfloat16* bw = g_wq + (size_t)(co0 + lrow) * 9 * CIN + lhalf * 32;

    const uint32_t dstA = sbase + (uint32_t)(lrow * PITCH + lhalf * 64);
    const uint32_t dstB = dstA + TILEB;

    const uint32_t a_lane = (uint32_t)((lane & 15) * PITCH + (lane >> 4) * 16);
    const uint32_t b_lane = (uint32_t)(((lane & 7) + ((lane >> 4) << 3)) * PITCH +
                                       (((lane >> 3) & 1) << 4));
    const uint32_t aBase0 = sbase + (warp_m * 32) * PITCH + a_lane;
    const uint32_t bBase0 = sbase + TILEB + (warp_n * 64) * PITCH + b_lane;

    float acc[2][8][4];
#pragma unroll
    for (int mi = 0; mi < 2; ++mi)
#pragma unroll
        for (int ni = 0; ni < 8; ++ni)
#pragma unroll
            for (int k = 0; k < 4; ++k) acc[mi][ni][k] = 0.0f;

    auto issue = [&](int c, int st) {
        int tap = c >> 2;
        int kc  = (c & 3) * 64;
        int kh  = tap / 3;
        int kw  = tap - kh * 3;
        int hi  = hb + kh, wi = wb + kw;
        bool v  = ((unsigned)hi < (unsigned)HIN) && ((unsigned)wi < (unsigned)WIN);
        const __nv_bfloat16* asrc = an + ((size_t)(hi * WIN + wi) * CIN + kc);
        const __nv_bfloat16* bsrc = bw + (tap * CIN + kc);
        uint32_t so = (uint32_t)(st * STGB);
#pragma unroll
        for (int i = 0; i < 4; ++i) {
            cp16(dstA + so + i * 16, v ? (const void*)(asrc + i * 8) : (const void*)g_xq,
                 v ? 16 : 0);
            cp16(dstB + so + i * 16, bsrc + i * 8, 16);
        }
    };

    issue(0, 0);
    asm volatile("cp.async.commit_group;\n" ::: "memory");

#pragma unroll 1
    for (int c = 0; c < 36; ++c) {
        if (c < 35) {
            issue(c + 1, (c + 1) & 1);
            asm volatile("cp.async.commit_group;\n" ::: "memory");
            asm volatile("cp.async.wait_group 1;\n" ::: "memory");
        } else {
            asm volatile("cp.async.wait_group 0;\n" ::: "memory");
        }
        __syncthreads();

        const uint32_t so = (uint32_t)((c & 1) * STGB);
        const uint32_t aB = aBase0 + so;
        const uint32_t bB = bBase0 + so;
#pragma unroll
        for (int ks = 0; ks < 4; ++ks) {
            const uint32_t kb = ks * 32;
            uint32_t a[2][4];
            LDSM4(a[0][0], a[0][1], a[0][2], a[0][3], aB + kb);
            LDSM4(a[1][0], a[1][1], a[1][2], a[1][3], aB + 16 * PITCH + kb);
#pragma unroll
            for (int p = 0; p < 4; ++p) {
                uint32_t b0, b1, b2, b3;
                LDSM4(b0, b1, b2, b3, bB + p * (16 * PITCH) + kb);
#pragma unroll
                for (int mi = 0; mi < 2; ++mi) {
                    MMABF16(acc[mi][2 * p],     a[mi], b0, b1);
                    MMABF16(acc[mi][2 * p + 1], a[mi], b2, b3);
                }
            }
        }
        __syncthreads();
    }

    const float sc = (float)(0.05 * 0.01);
#pragma unroll
    for (int mi = 0; mi < 2; ++mi) {
#pragma unroll
        for (int rr = 0; rr < 2; ++rr) {
            int mm = m0 + warp_m * 32 + mi * 16 + (lane >> 2) + rr * 8;
            int nn = mm / S_OUT;
            int ss = mm - nn * S_OUT;
            float* op = out + (size_t)nn * COUT * S_OUT + ss;
#pragma unroll
            for (int ni = 0; ni < 8; ++ni) {
                int co = co0 + warp_n * 64 + ni * 8 + (lane & 3) * 2;
                op[(size_t)co * S_OUT]       = acc[mi][ni][rr * 2 + 0] * sc;
                op[(size_t)(co + 1) * S_OUT] = acc[mi][ni][rr * 2 + 1] * sc;
            }
        }
    }
}

// ---- s8 ALU-path body (verbatim R4, smem rebased) ----
__device__ __forceinline__ void conv_s8_body(char* dsm, float* __restrict__ out) {
    const uint32_t sbase = (uint32_t)__cvta_generic_to_shared(dsm);
    // layout: A stage0, A stage1, B stage0, B stage1 (each STG8)
    const int t      = threadIdx.x;
    const int lane   = t & 31;
    const int warp_m = (t >> 5) & 3;
    const int warp_n = t >> 7;
    const int m0     = blockIdx.x * 128;
    const int co0    = blockIdx.y * 128;

    const int lrow = t >> 2;
    const int lseg = t & 3;

    long abase[2];
    int hi0[2], wi0[2];
    const signed char* bbase[2];
#pragma unroll
    for (int i = 0; i < 2; ++i) {
        int m   = m0 + lrow + i * 64;
        int n   = m / S_OUT;
        int rem = m - n * S_OUT;
        int ho  = rem / WOUT;
        int wo  = rem - ho * WOUT;
        hi0[i] = 2 * ho - 1;
        wi0[i] = 2 * wo - 1;
        abase[i] = ((long)n * S_IN + (long)hi0[i] * WIN + wi0[i]) * CIN + lseg * 16;
        bbase[i] = g_wq8 + (size_t)(co0 + lrow + i * 64) * 9 * CIN + lseg * 16;
    }

    const uint32_t dA0 = sbase + lrow * PITCH8 + lseg * 16;
    const uint32_t dB0 = sbase + 2 * STG8 + lrow * PITCH8 + lseg * 16;

    const uint32_t a_lane = (uint32_t)((lane & 15) * PITCH8 + (lane >> 4) * 16);
    const uint32_t b_lane = (uint32_t)(((lane & 7) + ((lane >> 4) << 3)) * PITCH8 +
                                       (((lane >> 3) & 1) << 4));
    const uint32_t aBase0 = sbase + (warp_m * 32) * PITCH8 + a_lane;
    const uint32_t bBase0 = sbase + 2 * STG8 + (warp_n * 64) * PITCH8 + b_lane;

    int acc[2][8][4];
#pragma unroll
    for (int mi = 0; mi < 2; ++mi)
#pragma unroll
        for (int ni = 0; ni < 8; ++ni)
#pragma unroll
            for (int k = 0; k < 4; ++k) acc[mi][ni][k] = 0;

    auto issue = [&](int c, int st) {
        int tap = c >> 2;
        int kc  = (c & 3) * 64;
        int kh  = tap / 3;
        int kw  = tap - kh * 3;
        uint32_t so = (uint32_t)(st * STG8);
#pragma unroll
        for (int i = 0; i < 2; ++i) {
            bool v = ((unsigned)(hi0[i] + kh) < (unsigned)HIN) &&
                     ((unsigned)(wi0[i] + kw) < (unsigned)WIN);
            long toff = (long)((kh * WIN + kw) * CIN + kc);
            const signed char* asrc = v ? (g_xq8 + abase[i] + toff) : g_xq8;
            cp16(dA0 + so + i * (64 * PITCH8), asrc, v ? 16 : 0);
            cp16(dB0 + so + i * (64 * PITCH8), bbase[i] + tap * CIN + kc, 16);
        }
    };

    issue(0, 0);
    asm volatile("cp.async.commit_group;\n" ::: "memory");

#pragma unroll 1
    for (int c = 0; c < 36; ++c) {
        if (c < 35) {
            issue(c + 1, (c + 1) & 1);
            asm volatile("cp.async.commit_group;\n" ::: "memory");
            asm volatile("cp.async.wait_group 1;\n" ::: "memory");
        } else {
            asm volatile("cp.async.wait_group 0;\n" ::: "memory");
        }
        __syncthreads();

        const uint32_t so = (uint32_t)((c & 1) * STG8);
        const uint32_t aB = aBase0 + so;
        const uint32_t bB = bBase0 + so;
#pragma unroll
        for (int k2 = 0; k2 < 2; ++k2) {
            const uint32_t kb = k2 * 32;
            uint32_t a[2][4];
            LDSM4(a[0][0], a[0][1], a[0][2], a[0][3], aB + kb);
            LDSM4(a[1][0], a[1][1], a[1][2], a[1][3], aB + 16 * PITCH8 + kb);
#pragma unroll
            for (int p = 0; p < 4; ++p) {
                uint32_t b0, b1, b2, b3;
                LDSM4(b0, b1, b2, b3, bB + p * (16 * PITCH8) + kb);
#pragma unroll
                for (int mi = 0; mi < 2; ++mi) {
                    MMAS8(acc[mi][2 * p],     a[mi], b0, b1);
                    MMAS8(acc[mi][2 * p + 1], a[mi], b2, b3);
                }
            }
        }
        __syncthreads();
    }

    const float sc = (float)(0.05 * 0.01);
#pragma unroll
    for (int mi = 0; mi < 2; ++mi) {
#pragma unroll
        for (int rr = 0; rr < 2; ++rr) {
            int mm = m0 + warp_m * 32 + mi * 16 + (lane >> 2) + rr * 8;
            int nn = mm / S_OUT;
            int ss = mm - nn * S_OUT;
            float* op = out + (size_t)nn * COUT * S_OUT + ss;
#pragma unroll
            for (int ni = 0; ni < 8; ++ni) {
                int co = co0 + warp_n * 64 + ni * 8 + (lane & 3) * 2;
                op[(size_t)co * S_OUT]       = (float)acc[mi][ni][rr * 2 + 0] * sc;
                op[(size_t)(co + 1) * S_OUT] = (float)acc[mi][ni][rr * 2 + 1] * sc;
            }
        }
    }
}

__global__ void __launch_bounds__(256, 2) conv_hybrid_kernel(float* __restrict__ out) {
    extern __shared__ char dsm[];
    if (blockIdx.x < NBF) conv_bf16_body(dsm, out);
    else                  conv_s8_body(dsm, out);
}

// ---------------------------------------------------------------------------
extern "C" void kernel_launch(void* const* d_in, const int* in_sizes, int n_in,
                              void* d_out, int out_size) {
    const float* x = (const float*)d_in[0];
    const float* w = (const float*)d_in[1];
    if (n_in >= 2 && in_sizes[0] != X_ELEMS) {
        const float* tmp = x; x = w; w = tmp;
    }
    float* out = (float*)d_out;

    dim3 g1(S_IN / 32, CIN / 128, XN);  // (98, 2, 32)
    quant_x_kernel<<<g1, 256>>>(x);

    quant_w_kernel<<<(COUT * 9 * CIN + 255) / 256, 256>>>(w);

    cudaFuncSetAttribute(conv_hybrid_kernel,
                         cudaFuncAttributeMaxDynamicSharedMemorySize, SMEMT);
    dim3 g3(NTILES, COUT / 128);  // (196, 2)
    conv_hybrid_kernel<<<g3, 256, SMEMT>>>(out);
}

// round 9
// speedup vs baseline: 1.2583x; 1.2583x over previous
#include <cuda_runtime.h>
#include <cuda_fp16.h>
#include <cstdint>

#define XN 32
#define CIN 256
#define HIN 56
#define WIN 56
#define S_IN 3136
#define COUT 256
#define HOUT 28
#define WOUT 28
#define S_OUT 784
#define M_TOTAL 25088
#define X_ELEMS (XN * CIN * S_IN)

// Device scratch (no cudaMalloc allowed)
__device__ __align__(16) __half       g_xh[(size_t)XN * S_IN * CIN];   // 51.4 MB NHWC fp16
__device__ __align__(16) signed char  g_x8[(size_t)XN * S_IN * CIN];   // 25.7 MB NHWC s8
__device__ __align__(16) __half       g_wh[(size_t)COUT * 9 * CIN];    // [co][tap][ci] fp16
__device__ __align__(16) signed char  g_w8[(size_t)COUT * 9 * CIN];    // [co][tap][ci] s8

// ---------------------------------------------------------------------------
// Kernel 1: quantize x -> fp16 NHWC + s8 NHWC. Two-phase smem reuse:
// phase A writes fp16 tile (q kept packed in regs), phase B reuses the same
// buffer as the s8 tile. smem 8.3KB, minimal occupancy impact.
// ---------------------------------------------------------------------------
__global__ void quant_x_kernel(const float* __restrict__ x) {
    __shared__ __align__(16) unsigned char tbuf[32 * 260];  // 8320 B, aliased
    __half*      th = (__half*)tbuf;        // pitch 130 halves (conflict-free)
    signed char* t8 = (signed char*)tbuf;   // pitch 132 bytes  (conflict-free)
    const int n  = blockIdx.z;
    const int c0 = blockIdx.y * 128;
    const int s0 = blockIdx.x * 32;
    const int t  = threadIdx.x;

    uint32_t qp[4] = {0, 0, 0, 0};
    const float* xb = x + (size_t)n * CIN * S_IN;
#pragma unroll
    for (int it = 0; it < 16; ++it) {
        int i  = it * 256 + t;
        int cl = i >> 5;
        int sl = i & 31;
        float v = xb[(size_t)(c0 + cl) * S_IN + (s0 + sl)];
        int q = __float2int_rn(v * 20.0f);   // round-half-even == jnp.round
        q = max(-128, min(127, q));
        th[sl * 130 + cl] = __int2half_rn(q);          // exact (|q|<=128)
        qp[it >> 2] |= ((uint32_t)(q & 0xff)) << (8 * (it & 3));
    }
    __syncthreads();

    __half* ob = g_xh + ((size_t)n * S_IN + s0) * CIN + c0;
#pragma unroll
    for (int it = 0; it < 8; ++it) {
        int u  = it * 256 + t;
        int sl = u >> 6;
        int cu = u & 63;
        uint32_t val = *(const uint32_t*)&th[sl * 130 + cu * 2];
        *(uint32_t*)&ob[(size_t)sl * CIN + cu * 2] = val;
    }
    __syncthreads();   // fp16 tile fully drained before overwrite

#pragma unroll
    for (int it = 0; it < 16; ++it) {
        int i  = it * 256 + t;
        int cl = i >> 5;
        int sl = i & 31;
        t8[sl * 132 + cl] = (signed char)((qp[it >> 2] >> (8 * (it & 3))) & 0xff);
    }
    __syncthreads();

    signed char* ob8 = g_x8 + ((size_t)n * S_IN + s0) * CIN + c0;
#pragma unroll
    for (int it = 0; it < 4; ++it) {
        int j  = it * 256 + t;
        int sl = j >> 5;
        int c4 = j & 31;
        uint32_t val = *(const uint32_t*)&t8[sl * 132 + c4 * 4];
        *(uint32_t*)&ob8[(size_t)sl * CIN + c4 * 4] = val;
    }
}

// ---------------------------------------------------------------------------
// Kernel 2: weights OIHW fp32 (int-valued) -> [co][tap][ci] fp16 + s8
// ---------------------------------------------------------------------------
__global__ void quant_w_kernel(const float* __restrict__ w) {
    int idx = blockIdx.x * blockDim.x + threadIdx.x;
    if (idx >= COUT * 9 * CIN) return;
    int co  = idx / (9 * CIN);
    int r   = idx - co * 9 * CIN;
    int tap = r >> 8;
    int ci  = r & 255;
    int q = __float2int_rn(w[(size_t)co * CIN * 9 + (size_t)ci * 9 + tap]);
    g_wh[idx] = __int2half_rn(q);
    g_w8[idx] = (signed char)q;
}

// ---------------------------------------------------------------------------
// Kernel 3: dual-crew conv. 512 threads/block, one 128x128 output tile.
// Warps 0-7 (tensor crew): fp16 HMMA on K-chunks ch[0:192) taps 0-4, ch[0:128)
// taps 5-8  (23 chunks). Warps 8-15 (s8 crew): emulated IMMA on the remaining
// 13 chunks. wid%4 puts one warp of each crew on every SMSP -> tensor and
// fma/alu pipes run concurrently. Exact integer partials merged via smem.
// ---------------------------------------------------------------------------
// fp16 crew smem (R6-proven): PITCH 144
#define PITCH 144
#define TILEB (128 * PITCH)          // 18432
#define STGH  (2 * TILEB)            // 36864 per stage (A+B)
// s8 crew smem (R4-proven): PITCH 80
#define PITCH8 80
#define A8B   (128 * PITCH8)         // 10240
#define STG8  (2 * A8B)              // 20480 per stage (A+B)
#define S8OFF (2 * STGH)             // 73728
#define SMEMT (S8OFF + 2 * STG8)     // 114688
#define NC_H  23
#define NC_8  13

__device__ __forceinline__ void cp16(uint32_t dst, const void* src, int sz) {
    asm volatile("cp.async.ca.shared.global [%0], [%1], 16, %2;\n"
                 :: "r"(dst), "l"(src), "r"(sz));
}
#define LDSM4(r0, r1, r2, r3, addr)                                          \
    asm volatile("ldmatrix.sync.aligned.m8n8.x4.shared.b16 {%0,%1,%2,%3}, [%4];" \
                 : "=r"(r0), "=r"(r1), "=r"(r2), "=r"(r3) : "r"(addr))
#define MMAF16(d, a, b0_, b1_)                                                \
    asm volatile(                                                             \
        "mma.sync.aligned.m16n8k16.row.col.f32.f16.f16.f32 "                 \
        "{%0,%1,%2,%3}, {%4,%5,%6,%7}, {%8,%9}, {%0,%1,%2,%3};\n"            \
        : "+f"(d[0]), "+f"(d[1]), "+f"(d[2]), "+f"(d[3])                     \
        : "r"(a[0]), "r"(a[1]), "r"(a[2]), "r"(a[3]), "r"(b0_), "r"(b1_))
#define MMAS8(d, a, b0_, b1_)                                                 \
    asm volatile(                                                             \
        "mma.sync.aligned.m16n8k32.row.col.s32.s8.s8.s32 "                   \
        "{%0,%1,%2,%3}, {%4,%5,%6,%7}, {%8,%9}, {%0,%1,%2,%3};\n"            \
        : "+r"(d[0]), "+r"(d[1]), "+r"(d[2]), "+r"(d[3])                     \
        : "r"(a[0]), "r"(a[1]), "r"(a[2]), "r"(a[3]), "r"(b0_), "r"(b1_))
#define BAR(id, cnt) asm volatile("bar.sync %0, %1;" :: "r"(id), "r"(cnt) : "memory")

// chunk schedules (tap, channel-offset)
__device__ __forceinline__ void sched_h(int c, int& tap, int& kc) {
    if (c < 15) { tap = c / 3; kc = (c - tap * 3) * 64; }
    else        { int c2 = c - 15; tap = 5 + (c2 >> 1); kc = (c2 & 1) * 64; }
}
__device__ __forceinline__ void sched_8(int c, int& tap, int& kc) {
    if (c < 5) { tap = c; kc = 192; }
    else       { int c2 = c - 5; tap = 5 + (c2 >> 1); kc = 128 + (c2 & 1) * 64; }
}

__global__ void __launch_bounds__(512, 1) conv_dual_kernel(float* __restrict__ out) {
    extern __shared__ char dsm[];
    const uint32_t sbase = (uint32_t)__cvta_generic_to_shared(dsm);
    const int t    = threadIdx.x;
    const int lane = t & 31;
    const int wid  = t >> 5;
    const int m0   = blockIdx.x * 128;
    const int co0  = blockIdx.y * 128;
    // padded s32 acc exchange buffer (overlaps fp16 stages; ordered by BAR 3/4)
    int* sacc = (int*)dsm;   // [128][130]

    if (wid < 8) {
        // ================= tensor crew (fp16) =================
        const int ct     = t;           // 0..255
        const int warp_m = wid & 3;
        const int warp_n = wid >> 2;
        const int lrow   = ct >> 1;
        const int lhalf  = ct & 1;

        int m   = m0 + lrow;
        int n   = m / S_OUT;
        int rem = m - n * S_OUT;
        int ho  = rem / WOUT;
        int wo  = rem - ho * WOUT;
        const int hb = 2 * ho - 1;
        const int wb = 2 * wo - 1;
        const __half* an = g_xh + (size_t)n * S_IN * CIN + lhalf * 32;
        const __half* bw = g_wh + (size_t)(co0 + lrow) * 9 * CIN + lhalf * 32;

        const uint32_t dstA = sbase + (uint32_t)(lrow * PITCH + lhalf * 64);
        const uint32_t dstB = dstA + TILEB;
        const uint32_t a_lane = (uint32_t)((lane & 15) * PITCH + (lane >> 4) * 16);
        const uint32_t b_lane = (uint32_t)(((lane & 7) + ((lane >> 4) << 3)) * PITCH +
                                           (((lane >> 3) & 1) << 4));
        const uint32_t aBase0 = sbase + (warp_m * 32) * PITCH + a_lane;
        const uint32_t bBase0 = sbase + TILEB + (warp_n * 64) * PITCH + b_lane;

        float acc[2][8][4];
#pragma unroll
        for (int mi = 0; mi < 2; ++mi)
#pragma unroll
            for (int ni = 0; ni < 8; ++ni)
#pragma unroll
                for (int k = 0; k < 4; ++k) acc[mi][ni][k] = 0.0f;

        auto issue = [&](int c, int st) {
            int tap, kc; sched_h(c, tap, kc);
            int kh = tap / 3, kw = tap - kh * 3;
            int hi = hb + kh, wi = wb + kw;
            bool v = ((unsigned)hi < (unsigned)HIN) && ((unsigned)wi < (unsigned)WIN);
            const __half* asrc = an + ((size_t)(hi * WIN + wi) * CIN + kc);
            const __half* bsrc = bw + (tap * CIN + kc);
            uint32_t so = (uint32_t)(st * STGH);
#pragma unroll
            for (int i = 0; i < 4; ++i) {
                cp16(dstA + so + i * 16,
                     v ? (const void*)(asrc + i * 8) : (const void*)g_xh, v ? 16 : 0);
                cp16(dstB + so + i * 16, bsrc + i * 8, 16);
            }
        };

        issue(0, 0);
        asm volatile("cp.async.commit_group;\n" ::: "memory");

#pragma unroll 1
        for (int c = 0; c < NC_H; ++c) {
            if (c < NC_H - 1) {
                issue(c + 1, (c + 1) & 1);
                asm volatile("cp.async.commit_group;\n" ::: "memory");
                asm volatile("cp.async.wait_group 1;\n" ::: "memory");
            } else {
                asm volatile("cp.async.wait_group 0;\n" ::: "memory");
            }
            BAR(1, 256);
            const uint32_t so = (uint32_t)((c & 1) * STGH);
            const uint32_t aB = aBase0 + so;
            const uint32_t bB = bBase0 + so;
#pragma unroll
            for (int ks = 0; ks < 4; ++ks) {
                const uint32_t kb = ks * 32;
                uint32_t a[2][4];
                LDSM4(a[0][0], a[0][1], a[0][2], a[0][3], aB + kb);
                LDSM4(a[1][0], a[1][1], a[1][2], a[1][3], aB + 16 * PITCH + kb);
#pragma unroll
                for (int p = 0; p < 4; ++p) {
                    uint32_t b0, b1, b2, b3;
                    LDSM4(b0, b1, b2, b3, bB + p * (16 * PITCH) + kb);
#pragma unroll
                    for (int mi = 0; mi < 2; ++mi) {
                        MMAF16(acc[mi][2 * p],     a[mi], b0, b1);
                        MMAF16(acc[mi][2 * p + 1], a[mi], b2, b3);
                    }
                }
            }
            BAR(1, 256);
        }

        // wait for s8 crew's partials, then merge + store
        BAR(3, 512);   // fp16 stages now dead everywhere
        BAR(4, 512);   // s8 partials visible in sacc
        const float sc = (float)(0.05 * 0.01);
#pragma unroll
        for (int mi = 0; mi < 2; ++mi) {
#pragma unroll
            for (int rr = 0; rr < 2; ++rr) {
                int row = warp_m * 32 + mi * 16 + (lane >> 2) + rr * 8;
                int mm  = m0 + row;
                int nn  = mm / S_OUT;
                int ss  = mm - nn * S_OUT;
                float* op = out + (size_t)nn * COUT * S_OUT + ss;
#pragma unroll
                for (int ni = 0; ni < 8; ++ni) {
                    int col = warp_n * 64 + ni * 8 + (lane & 3) * 2;
                    int co  = co0 + col;
                    float v0 = acc[mi][ni][rr * 2 + 0] + (float)sacc[row * 130 + col];
                    float v1 = acc[mi][ni][rr * 2 + 1] + (float)sacc[row * 130 + col + 1];
                    op[(size_t)co * S_OUT]       = v0 * sc;
                    op[(size_t)(co + 1) * S_OUT] = v1 * sc;
                }
            }
        }
    } else {
        // ================= s8 crew (fma/alu pipes) =================
        const int ct     = t - 256;     // 0..255
        const int cw     = wid - 8;
        const int warp_m = cw & 3;
        const int warp_n = cw >> 2;
        const int lrow   = ct >> 2;
        const int lseg   = ct & 3;

        long abase[2];
        int hi0[2], wi0[2];
        const signed char* bbase[2];
#pragma unroll
        for (int i = 0; i < 2; ++i) {
            int m   = m0 + lrow + i * 64;
            int n   = m / S_OUT;
            int rem = m - n * S_OUT;
            int ho  = rem / WOUT;
            int wo  = rem - ho * WOUT;
            hi0[i] = 2 * ho - 1;
            wi0[i] = 2 * wo - 1;
            abase[i] = ((long)n * S_IN + (long)hi0[i] * WIN + wi0[i]) * CIN + lseg * 16;
            bbase[i] = g_w8 + (size_t)(co0 + lrow + i * 64) * 9 * CIN + lseg * 16;
        }

        const uint32_t s8b = sbase + S8OFF;
        const uint32_t dA0 = s8b + lrow * PITCH8 + lseg * 16;
        const uint32_t dB0 = s8b + A8B + lrow * PITCH8 + lseg * 16;
        const uint32_t a_lane = (uint32_t)((lane & 15) * PITCH8 + (lane >> 4) * 16);
        const uint32_t b_lane = (uint32_t)(((lane & 7) + ((lane >> 4) << 3)) * PITCH8 +
                                           (((lane >> 3) & 1) << 4));
        const uint32_t aBase0 = s8b + (warp_m * 32) * PITCH8 + a_lane;
        const uint32_t bBase0 = s8b + A8B + (warp_n * 64) * PITCH8 + b_lane;

        int acc[2][8][4];
#pragma unroll
        for (int mi = 0; mi < 2; ++mi)
#pragma unroll
            for (int ni = 0; ni < 8; ++ni)
#pragma unroll
                for (int k = 0; k < 4; ++k) acc[mi][ni][k] = 0;

        auto issue = [&](int c, int st) {
            int tap, kc; sched_8(c, tap, kc);
            int kh = tap / 3, kw = tap - kh * 3;
            uint32_t so = (uint32_t)(st * STG8);
#pragma unroll
            for (int i = 0; i < 2; ++i) {
                bool v = ((unsigned)(hi0[i] + kh) < (unsigned)HIN) &&
                         ((unsigned)(wi0[i] + kw) < (unsigned)WIN);
                long toff = (long)((kh * WIN + kw) * CIN + kc);
                const signed char* asrc = v ? (g_x8 + abase[i] + toff) : g_x8;
                cp16(dA0 + so + i * (64 * PITCH8), asrc, v ? 16 : 0);
                cp16(dB0 + so + i * (64 * PITCH8), bbase[i] + tap * CIN + kc, 16);
            }
        };

        issue(0, 0);
        asm volatile("cp.async.commit_group;\n" ::: "memory");

#pragma unroll 1
        for (int c = 0; c < NC_8; ++c) {
            if (c < NC_8 - 1) {
                issue(c + 1, (c + 1) & 1);
                asm volatile("cp.async.commit_group;\n" ::: "memory");
                asm volatile("cp.async.wait_group 1;\n" ::: "memory");
            } else {
                asm volatile("cp.async.wait_group 0;\n" ::: "memory");
            }
            BAR(2, 256);
            const uint32_t so = (uint32_t)((c & 1) * STG8);
            const uint32_t aB = aBase0 + so;
            const uint32_t bB = bBase0 + so;
#pragma unroll
            for (int k2 = 0; k2 < 2; ++k2) {
                const uint32_t kb = k2 * 32;
                uint32_t a[2][4];
                LDSM4(a[0][0], a[0][1], a[0][2], a[0][3], aB + kb);
                LDSM4(a[1][0], a[1][1], a[1][2], a[1][3], aB + 16 * PITCH8 + kb);
#pragma unroll
                for (int p = 0; p < 4; ++p) {
                    uint32_t b0, b1, b2, b3;
                    LDSM4(b0, b1, b2, b3, bB + p * (16 * PITCH8) + kb);
#pragma unroll
                    for (int mi = 0; mi < 2; ++mi) {
                        MMAS8(acc[mi][2 * p],     a[mi], b0, b1);
                        MMAS8(acc[mi][2 * p + 1], a[mi], b2, b3);
                    }
                }
            }
            BAR(2, 256);
        }

        // publish partials after fp16 crew is done with its stage buffers
        BAR(3, 512);
#pragma unroll
        for (int mi = 0; mi < 2; ++mi)
#pragma unroll
            for (int rr = 0; rr < 2; ++rr) {
                int row = warp_m * 32 + mi * 16 + (lane >> 2) + rr * 8;
#pragma unroll
                for (int ni = 0; ni < 8; ++ni) {
                    int col = warp_n * 64 + ni * 8 + (lane & 3) * 2;
                    sacc[row * 130 + col]     = acc[mi][ni][rr * 2 + 0];
                    sacc[row * 130 + col + 1] = acc[mi][ni][rr * 2 + 1];
                }
            }
        BAR(4, 512);
    }
}

// ---------------------------------------------------------------------------
extern "C" void kernel_launch(void* const* d_in, const int* in_sizes, int n_in,
                              void* d_out, int out_size) {
    const float* x = (const float*)d_in[0];
    const float* w = (const float*)d_in[1];
    if (n_in >= 2 && in_sizes[0] != X_ELEMS) {
        const float* tmp = x; x = w; w = tmp;
    }
    float* out = (float*)d_out;

    dim3 g1(S_IN / 32, CIN / 128, XN);  // (98, 2, 32)
    quant_x_kernel<<<g1, 256>>>(x);

    quant_w_kernel<<<(COUT * 9 * CIN + 255) / 256, 256>>>(w);

    cudaFuncSetAttribute(conv_dual_kernel,
                         cudaFuncAttributeMaxDynamicSharedMemorySize, SMEMT);
    dim3 g3(M_TOTAL / 128, COUT / 128);  // (196, 2)
    conv_dual_kernel<<<g3, 512, SMEMT>>>(out);
}